// round 1
// baseline (speedup 1.0000x reference)
#include <cuda_runtime.h>
#include <math.h>

#define BT   4096      // B*T
#define HID  1024
#define TSEQ 2048
#define KVW  512       // 2 * N_KV_HEADS * HEAD_DIM
#define HD   64

// Scratch (device globals — no allocation allowed)
__device__ float g_q[(size_t)BT * HID];
__device__ float g_kv[(size_t)BT * KVW];
__device__ float g_att[(size_t)BT * HID];

// ---------------------------------------------------------------------------
// SGEMM: C[M,N] = A[M,K] @ B[K,N].  BM=128, BN=64, BK=16, 256 thr, 8x4/thread
// ---------------------------------------------------------------------------
__global__ __launch_bounds__(256) void sgemm_kernel(
    const float* __restrict__ A, const float* __restrict__ B,
    float* __restrict__ C, int M, int N, int K)
{
    __shared__ float sA[16][128];  // [k][m] (transposed)
    __shared__ float sB[16][64];   // [k][n]

    const int t  = threadIdx.x;
    const int m0 = blockIdx.y * 128;
    const int n0 = blockIdx.x * 64;
    const int tr = t >> 4;   // 0..15 -> rows tr*8..tr*8+7
    const int tc = t & 15;   // 0..15 -> cols tc*4..tc*4+3

    float acc[8][4];
    #pragma unroll
    for (int i = 0; i < 8; i++)
        #pragma unroll
        for (int j = 0; j < 4; j++) acc[i][j] = 0.f;

    for (int k0 = 0; k0 < K; k0 += 16) {
        // A tile: 128x16 = 512 float4, 2 per thread, store transposed
        #pragma unroll
        for (int u = 0; u < 2; u++) {
            int id  = t + 256 * u;
            int row = id >> 2;
            int kq  = id & 3;
            float4 v = *(const float4*)(A + (size_t)(m0 + row) * K + k0 + kq * 4);
            sA[kq * 4 + 0][row] = v.x;
            sA[kq * 4 + 1][row] = v.y;
            sA[kq * 4 + 2][row] = v.z;
            sA[kq * 4 + 3][row] = v.w;
        }
        // B tile: 16x64 = 256 float4, 1 per thread, direct
        {
            int kk = t >> 4;
            int nq = t & 15;
            *(float4*)(&sB[kk][nq * 4]) =
                *(const float4*)(B + (size_t)(k0 + kk) * N + n0 + nq * 4);
        }
        __syncthreads();

        #pragma unroll
        for (int kk = 0; kk < 16; kk++) {
            float a[8], bb[4];
            #pragma unroll
            for (int i = 0; i < 2; i++) {
                float4 v = *(float4*)(&sA[kk][tr * 8 + i * 4]);
                a[i*4+0] = v.x; a[i*4+1] = v.y; a[i*4+2] = v.z; a[i*4+3] = v.w;
            }
            float4 w = *(float4*)(&sB[kk][tc * 4]);
            bb[0] = w.x; bb[1] = w.y; bb[2] = w.z; bb[3] = w.w;
            #pragma unroll
            for (int i = 0; i < 8; i++)
                #pragma unroll
                for (int j = 0; j < 4; j++)
                    acc[i][j] += a[i] * bb[j];
        }
        __syncthreads();
    }

    #pragma unroll
    for (int i = 0; i < 8; i++) {
        float4 v = make_float4(acc[i][0], acc[i][1], acc[i][2], acc[i][3]);
        *(float4*)(C + (size_t)(m0 + tr * 8 + i) * N + n0 + tc * 4) = v;
    }
}

// ---------------------------------------------------------------------------
// Causal flash attention, fp32. Grid: (T/64, H, B), 256 threads.
// Each CTA: 64 q-rows of one head. k-tiles of 64, online softmax.
// Thread (tr,tc) owns S/P rows 4tr..4tr+3, cols 4tc..4tc+3.
// ---------------------------------------------------------------------------
__global__ __launch_bounds__(256) void attn_kernel(
    const float* __restrict__ q, const float* __restrict__ kv,
    float* __restrict__ o)
{
    __shared__ float sQ[64][64];   // [d][r] transposed
    __shared__ float sKP[64][64];  // K as [d][c], later reused as P [r][c]
    __shared__ float sV[64][64];   // [c][d]

    const int t  = threadIdx.x;
    const int qt = blockIdx.x;
    const int h  = blockIdx.y;
    const int b  = blockIdx.z;
    const int kvh = h >> 2;   // GQA: 4 q-heads per kv-head
    const int tr = t >> 4;
    const int tc = t & 15;

    const size_t qbase  = (size_t)b * TSEQ * HID + (size_t)h * HD;
    const size_t kvbase = (size_t)b * TSEQ * KVW + (size_t)kvh * HD;

    // Load Q tile transposed: sQ[d][r]
    #pragma unroll
    for (int u = 0; u < 4; u++) {
        int id = t + 256 * u;       // 0..1023 float4 slots
        int r  = id >> 4;
        int dq = id & 15;
        float4 v = *(const float4*)(q + qbase + (size_t)(qt * 64 + r) * HID + dq * 4);
        sQ[dq * 4 + 0][r] = v.x;
        sQ[dq * 4 + 1][r] = v.y;
        sQ[dq * 4 + 2][r] = v.z;
        sQ[dq * 4 + 3][r] = v.w;
    }

    float m[4], l[4], O[4][4];
    #pragma unroll
    for (int i = 0; i < 4; i++) {
        m[i] = -INFINITY; l[i] = 0.f;
        #pragma unroll
        for (int j = 0; j < 4; j++) O[i][j] = 0.f;
    }
    const float scale = 0.125f;  // 1/sqrt(64)

    for (int kt = 0; kt <= qt; kt++) {
        __syncthreads();  // previous PV reads done (and Q visible on iter 0)

        // Load K tile transposed (sKP[d][c]) and V tile direct (sV[c][d])
        #pragma unroll
        for (int u = 0; u < 4; u++) {
            int id = t + 256 * u;
            int c  = id >> 4;
            int dq = id & 15;
            const float* row = kv + kvbase + (size_t)(kt * 64 + c) * KVW;
            float4 kk4 = *(const float4*)(row + dq * 4);
            sKP[dq * 4 + 0][c] = kk4.x;
            sKP[dq * 4 + 1][c] = kk4.y;
            sKP[dq * 4 + 2][c] = kk4.z;
            sKP[dq * 4 + 3][c] = kk4.w;
            *(float4*)(&sV[c][dq * 4]) = *(const float4*)(row + 256 + dq * 4);
        }
        __syncthreads();

        // S = Q K^T (4x4 per thread)
        float s[4][4];
        #pragma unroll
        for (int i = 0; i < 4; i++)
            #pragma unroll
            for (int j = 0; j < 4; j++) s[i][j] = 0.f;

        #pragma unroll 8
        for (int kk = 0; kk < 64; kk++) {
            float4 a = *(float4*)(&sQ[kk][tr * 4]);
            float4 bb = *(float4*)(&sKP[kk][tc * 4]);
            float av[4] = {a.x, a.y, a.z, a.w};
            float bv[4] = {bb.x, bb.y, bb.z, bb.w};
            #pragma unroll
            for (int i = 0; i < 4; i++)
                #pragma unroll
                for (int j = 0; j < 4; j++)
                    s[i][j] += av[i] * bv[j];
        }

        // scale + causal mask (only the diagonal tile has masked entries)
        #pragma unroll
        for (int i = 0; i < 4; i++)
            #pragma unroll
            for (int j = 0; j < 4; j++) {
                s[i][j] *= scale;
                if (kt == qt) {
                    int qi = qt * 64 + tr * 4 + i;
                    int kj = kt * 64 + tc * 4 + j;
                    if (kj > qi) s[i][j] = -INFINITY;
                }
            }

        // online softmax per row (16-lane row group = same tr, all tc)
        #pragma unroll
        for (int i = 0; i < 4; i++) {
            float mx = fmaxf(fmaxf(s[i][0], s[i][1]), fmaxf(s[i][2], s[i][3]));
            #pragma unroll
            for (int off = 1; off < 16; off <<= 1)
                mx = fmaxf(mx, __shfl_xor_sync(0xffffffffu, mx, off));
            float mn = fmaxf(m[i], mx);
            float alpha = __expf(m[i] - mn);
            float rs = 0.f;
            #pragma unroll
            for (int j = 0; j < 4; j++) {
                float p = __expf(s[i][j] - mn);
                s[i][j] = p;
                rs += p;
            }
            #pragma unroll
            for (int off = 1; off < 16; off <<= 1)
                rs += __shfl_xor_sync(0xffffffffu, rs, off);
            l[i] = l[i] * alpha + rs;
            m[i] = mn;
            #pragma unroll
            for (int j = 0; j < 4; j++) O[i][j] *= alpha;
        }

        __syncthreads();  // everyone done reading sKP as K

        // write P into sKP as [r][c]
        #pragma unroll
        for (int i = 0; i < 4; i++)
            *(float4*)(&sKP[tr * 4 + i][tc * 4]) =
                make_float4(s[i][0], s[i][1], s[i][2], s[i][3]);
        __syncthreads();

        // O += P @ V  (thread owns O rows 4tr.., d-cols 4tc..)
        #pragma unroll 8
        for (int c = 0; c < 64; c++) {
            float4 vv = *(float4*)(&sV[c][tc * 4]);
            float vrow[4] = {vv.x, vv.y, vv.z, vv.w};
            float pr[4];
            #pragma unroll
            for (int i = 0; i < 4; i++) pr[i] = sKP[tr * 4 + i][c];
            #pragma unroll
            for (int i = 0; i < 4; i++)
                #pragma unroll
                for (int j = 0; j < 4; j++)
                    O[i][j] += pr[i] * vrow[j];
        }
    }

    // epilogue: O /= l, store to [b,t,h*64+d] layout
    #pragma unroll
    for (int i = 0; i < 4; i++) {
        float inv = 1.f / l[i];
        int qi = qt * 64 + tr * 4 + i;
        float4 v = make_float4(O[i][0] * inv, O[i][1] * inv,
                               O[i][2] * inv, O[i][3] * inv);
        *(float4*)(o + (size_t)(b * TSEQ + qi) * HID + h * HD + tc * 4) = v;
    }
}

// ---------------------------------------------------------------------------
extern "C" void kernel_launch(void* const* d_in, const int* in_sizes, int n_in,
                              void* d_out, int out_size)
{
    const float* x   = (const float*)d_in[0];  // [2,2048,1024]
    const float* Wq  = (const float*)d_in[1];  // [1024,1024]
    const float* Wkv = (const float*)d_in[2];  // [1024,512]
    const float* Wo  = (const float*)d_in[3];  // [1024,1024]
    float* out = (float*)d_out;                // [2,2048,1024]

    float *gq, *gkv, *gatt;
    cudaGetSymbolAddress((void**)&gq, g_q);
    cudaGetSymbolAddress((void**)&gkv, g_kv);
    cudaGetSymbolAddress((void**)&gatt, g_att);

    dim3 blk(256);
    // q = x @ Wq : [4096,1024]
    sgemm_kernel<<<dim3(1024 / 64, BT / 128), blk>>>(x, Wq, gq, BT, HID, HID);
    // kv = x @ Wkv : [4096,512]
    sgemm_kernel<<<dim3(KVW / 64, BT / 128), blk>>>(x, Wkv, gkv, BT, KVW, HID);
    // causal GQA attention
    attn_kernel<<<dim3(TSEQ / 64, 16, 2), blk>>>(gq, gkv, gatt);
    // out = att @ Wo
    sgemm_kernel<<<dim3(HID / 64, BT / 128), blk>>>(gatt, Wo, out, BT, HID, HID);
}

// round 4
// speedup vs baseline: 3.0104x; 3.0104x over previous
#include <cuda_runtime.h>
#include <math.h>

#define BT   4096
#define HID  1024
#define TSEQ 2048
#define KVW  512
#define HD   64

__device__ float g_q[(size_t)BT * HID];
__device__ float g_kv[(size_t)BT * KVW];
__device__ float g_att[(size_t)BT * HID];

// ---------------------------------------------------------------------------
// tf32 helpers
// ---------------------------------------------------------------------------
__device__ __forceinline__ unsigned f2tf(float x) {
    unsigned r;
    asm("cvt.rna.tf32.f32 %0, %1;" : "=r"(r) : "f"(x));
    return r;
}
__device__ __forceinline__ void mma8(float* d, const unsigned* a, const unsigned* b) {
    asm volatile(
        "mma.sync.aligned.m16n8k8.row.col.f32.tf32.tf32.f32 "
        "{%0,%1,%2,%3},{%4,%5,%6,%7},{%8,%9},{%0,%1,%2,%3};\n"
        : "+f"(d[0]), "+f"(d[1]), "+f"(d[2]), "+f"(d[3])
        : "r"(a[0]), "r"(a[1]), "r"(a[2]), "r"(a[3]), "r"(b[0]), "r"(b[1]));
}
__device__ __forceinline__ void ldsm4(unsigned* r, unsigned addr) {
    asm volatile("ldmatrix.sync.aligned.m8n8.x4.shared.b16 {%0,%1,%2,%3}, [%4];"
                 : "=r"(r[0]), "=r"(r[1]), "=r"(r[2]), "=r"(r[3]) : "r"(addr));
}
__device__ __forceinline__ void ldsm2(unsigned* r, unsigned addr) {
    asm volatile("ldmatrix.sync.aligned.m8n8.x2.shared.b16 {%0,%1}, [%2];"
                 : "=r"(r[0]), "=r"(r[1]) : "r"(addr));
}
__device__ __forceinline__ unsigned sptr(const void* p) {
    return (unsigned)__cvta_generic_to_shared(p);
}

// ---------------------------------------------------------------------------
// tf32 GEMM core: C[M,N] = A[M,K] @ B[K,N]. BM=128, BN=64, BK=32, 256 threads
// (8 warps, 4x2 warp grid; warp tile 32x32 = 2 mfrag x 4 nfrag of m16n8).
// ---------------------------------------------------------------------------
#define GAS 36   // sA row stride (unsigned): 32 + 4 pad
#define GBS 68   // sB row stride (unsigned): 64 + 4 pad

__device__ __forceinline__ void gemm_core(
    const float* __restrict__ A, const float* __restrict__ B,
    float* __restrict__ C, int m0, int n0, int N, int K,
    unsigned* sA, unsigned* sB)
{
    const int t = threadIdx.x, lane = t & 31, warp = t >> 5;
    const int wm = warp & 3, wn = warp >> 2;
    const int g = lane >> 2, tig = lane & 3;

    float acc[2][4][4] = {};

    for (int k0 = 0; k0 < K; k0 += 32) {
        #pragma unroll
        for (int u = 0; u < 4; u++) {
            int id = t + 256 * u;
            int row = id >> 3, kq = id & 7;
            float4 v = *(const float4*)(A + (size_t)(m0 + row) * K + k0 + kq * 4);
            unsigned* d = &sA[row * GAS + kq * 4];
            d[0] = f2tf(v.x); d[1] = f2tf(v.y); d[2] = f2tf(v.z); d[3] = f2tf(v.w);
        }
        #pragma unroll
        for (int u = 0; u < 2; u++) {
            int id = t + 256 * u;
            int kr = id >> 4, nq = id & 15;
            float4 v = *(const float4*)(B + (size_t)(k0 + kr) * N + n0 + nq * 4);
            unsigned* d = &sB[kr * GBS + nq * 4];
            d[0] = f2tf(v.x); d[1] = f2tf(v.y); d[2] = f2tf(v.z); d[3] = f2tf(v.w);
        }
        __syncthreads();

        #pragma unroll
        for (int ks = 0; ks < 4; ks++) {
            unsigned af[2][4];
            #pragma unroll
            for (int mf = 0; mf < 2; mf++) {
                int row = wm * 32 + mf * 16 + (lane & 15);
                int col = ks * 8 + (lane >> 4) * 4;
                ldsm4(af[mf], sptr(&sA[row * GAS + col]));
            }
            #pragma unroll
            for (int nf = 0; nf < 4; nf++) {
                unsigned bv[2];
                int nc = wn * 32 + nf * 8 + g;
                bv[0] = sB[(ks * 8 + tig) * GBS + nc];
                bv[1] = sB[(ks * 8 + tig + 4) * GBS + nc];
                #pragma unroll
                for (int mf = 0; mf < 2; mf++)
                    mma8(acc[mf][nf], af[mf], bv);
            }
        }
        __syncthreads();
    }

    #pragma unroll
    for (int mf = 0; mf < 2; mf++)
        #pragma unroll
        for (int nf = 0; nf < 4; nf++) {
            int r = m0 + wm * 32 + mf * 16 + g;
            int c = n0 + wn * 32 + nf * 8 + tig * 2;
            *(float2*)(C + (size_t)r * N + c) =
                make_float2(acc[mf][nf][0], acc[mf][nf][1]);
            *(float2*)(C + (size_t)(r + 8) * N + c) =
                make_float2(acc[mf][nf][2], acc[mf][nf][3]);
        }
}

// Generic GEMM launch wrapper
__global__ __launch_bounds__(256) void gemm_tf32(
    const float* __restrict__ A, const float* __restrict__ B,
    float* __restrict__ C, int N, int K)
{
    __shared__ unsigned sA[128 * GAS];
    __shared__ unsigned sB[32 * GBS];
    gemm_core(A, B, C, blockIdx.y * 128, blockIdx.x * 64, N, K, sA, sB);
}

// Fused Q + KV projection: blockIdx.x 0..15 -> Wq (N=1024), 16..23 -> Wkv (N=512)
__global__ __launch_bounds__(256) void gemm_qkv(
    const float* __restrict__ x,
    const float* __restrict__ Wq, const float* __restrict__ Wkv,
    float* __restrict__ q, float* __restrict__ kvo)
{
    __shared__ unsigned sA[128 * GAS];
    __shared__ unsigned sB[32 * GBS];
    int bx = blockIdx.x;
    if (bx < 16)
        gemm_core(x, Wq, q, blockIdx.y * 128, bx * 64, HID, HID, sA, sB);
    else
        gemm_core(x, Wkv, kvo, blockIdx.y * 128, (bx - 16) * 64, KVW, HID, sA, sB);
}

// ---------------------------------------------------------------------------
// tf32 flash attention. Grid (T/64, H, B), 128 threads (4 warps).
// Warp w owns q-rows [w*16, w*16+16). Q frags in registers, sQP reused for P.
// ---------------------------------------------------------------------------
#define ASTR 68
#define ATT_SMEM (3 * 64 * ASTR * 4)

__global__ __launch_bounds__(128) void attn_tf32(
    const float* __restrict__ q, const float* __restrict__ kv,
    float* __restrict__ o)
{
    extern __shared__ unsigned smem[];
    unsigned* sQP = smem;                 // Q (prologue) then P [r][c]
    unsigned* sK  = smem + 64 * ASTR;     // [c][d]
    unsigned* sV  = smem + 2 * 64 * ASTR; // [c][d]

    const int t = threadIdx.x, lane = t & 31, warp = t >> 5;
    const int g = lane >> 2, tig = lane & 3;
    const int qt = gridDim.x - 1 - blockIdx.x;  // long tiles first
    const int h = blockIdx.y, b = blockIdx.z;
    const int kvh = h >> 2;

    const size_t qbase  = (size_t)b * TSEQ * HID + (size_t)h * HD;
    const size_t kvbase = (size_t)b * TSEQ * KVW + (size_t)kvh * HD;

    // Q tile (pre-scaled by 1/8 = hd^-0.5) -> sQP
    #pragma unroll
    for (int u = 0; u < 8; u++) {
        int id = t + 128 * u;
        int r = id >> 4, dq = id & 15;
        float4 v = *(const float4*)(q + qbase + (size_t)(qt * 64 + r) * HID + dq * 4);
        unsigned* d = &sQP[r * ASTR + dq * 4];
        d[0] = f2tf(v.x * 0.125f); d[1] = f2tf(v.y * 0.125f);
        d[2] = f2tf(v.z * 0.125f); d[3] = f2tf(v.w * 0.125f);
    }
    __syncthreads();

    // Q fragments to registers (sQP free after this)
    unsigned qa[8][4];
    {
        int row = warp * 16 + (lane & 15);
        int cb = (lane >> 4) * 4;
        #pragma unroll
        for (int ks = 0; ks < 8; ks++)
            ldsm4(qa[ks], sptr(&sQP[row * ASTR + ks * 8 + cb]));
    }

    float mr0 = -INFINITY, mr1 = -INFINITY, l0 = 0.f, l1 = 0.f;
    float O[8][4] = {};

    for (int kt = 0; kt <= qt; kt++) {
        __syncthreads();  // all warps done with sK/sV (and sQP frags loaded)

        // K and V tiles (64x64 each), natural [c][d] layout
        #pragma unroll
        for (int u = 0; u < 8; u++) {
            int id = t + 128 * u;
            int r = id >> 4, dq = id & 15;
            const float* rowp = kv + kvbase + (size_t)(kt * 64 + r) * KVW;
            float4 kk = *(const float4*)(rowp + dq * 4);
            unsigned* dk = &sK[r * ASTR + dq * 4];
            dk[0] = f2tf(kk.x); dk[1] = f2tf(kk.y); dk[2] = f2tf(kk.z); dk[3] = f2tf(kk.w);
            float4 vv = *(const float4*)(rowp + 256 + dq * 4);
            unsigned* dv = &sV[r * ASTR + dq * 4];
            dv[0] = f2tf(vv.x); dv[1] = f2tf(vv.y); dv[2] = f2tf(vv.z); dv[3] = f2tf(vv.w);
        }
        __syncthreads();

        // S = Q K^T (warp: 16 x 64)
        float s[8][4] = {};
        #pragma unroll
        for (int ks = 0; ks < 8; ks++) {
            #pragma unroll
            for (int nf = 0; nf < 8; nf++) {
                unsigned bf[2];
                int r = nf * 8 + (lane & 7);
                int c = ks * 8 + ((lane >> 3) & 1) * 4;
                ldsm2(bf, sptr(&sK[r * ASTR + c]));
                mma8(s[nf], qa[ks], bf);
            }
        }

        // causal mask (diagonal tile only)
        if (kt == qt) {
            int r0 = qt * 64 + warp * 16 + g;
            #pragma unroll
            for (int nf = 0; nf < 8; nf++) {
                int col = kt * 64 + nf * 8 + tig * 2;
                if (col     > r0)     s[nf][0] = -INFINITY;
                if (col + 1 > r0)     s[nf][1] = -INFINITY;
                if (col     > r0 + 8) s[nf][2] = -INFINITY;
                if (col + 1 > r0 + 8) s[nf][3] = -INFINITY;
            }
        }

        // online softmax: thread owns rows g (regs 0,1) and g+8 (regs 2,3)
        float mx0 = -INFINITY, mx1 = -INFINITY;
        #pragma unroll
        for (int nf = 0; nf < 8; nf++) {
            mx0 = fmaxf(mx0, fmaxf(s[nf][0], s[nf][1]));
            mx1 = fmaxf(mx1, fmaxf(s[nf][2], s[nf][3]));
        }
        #pragma unroll
        for (int off = 1; off < 4; off <<= 1) {
            mx0 = fmaxf(mx0, __shfl_xor_sync(0xffffffffu, mx0, off));
            mx1 = fmaxf(mx1, __shfl_xor_sync(0xffffffffu, mx1, off));
        }
        float nm0 = fmaxf(mr0, mx0), nm1 = fmaxf(mr1, mx1);
        float a0 = __expf(mr0 - nm0), a1 = __expf(mr1 - nm1);
        float rs0 = 0.f, rs1 = 0.f;
        #pragma unroll
        for (int nf = 0; nf < 8; nf++) {
            s[nf][0] = __expf(s[nf][0] - nm0);
            s[nf][1] = __expf(s[nf][1] - nm0);
            s[nf][2] = __expf(s[nf][2] - nm1);
            s[nf][3] = __expf(s[nf][3] - nm1);
            rs0 += s[nf][0] + s[nf][1];
            rs1 += s[nf][2] + s[nf][3];
        }
        #pragma unroll
        for (int off = 1; off < 4; off <<= 1) {
            rs0 += __shfl_xor_sync(0xffffffffu, rs0, off);
            rs1 += __shfl_xor_sync(0xffffffffu, rs1, off);
        }
        l0 = l0 * a0 + rs0;  l1 = l1 * a1 + rs1;
        mr0 = nm0;           mr1 = nm1;
        #pragma unroll
        for (int df = 0; df < 8; df++) {
            O[df][0] *= a0; O[df][1] *= a0;
            O[df][2] *= a1; O[df][3] *= a1;
        }

        // P -> sQP (warp-private rows), tf32
        {
            int r = warp * 16 + g;
            #pragma unroll
            for (int nf = 0; nf < 8; nf++) {
                int c = nf * 8 + tig * 2;
                *(uint2*)&sQP[r * ASTR + c] =
                    make_uint2(f2tf(s[nf][0]), f2tf(s[nf][1]));
                *(uint2*)&sQP[(r + 8) * ASTR + c] =
                    make_uint2(f2tf(s[nf][2]), f2tf(s[nf][3]));
            }
        }
        __syncwarp();

        // O += P @ V
        #pragma unroll
        for (int ks = 0; ks < 8; ks++) {
            unsigned pa[4];
            int row = warp * 16 + (lane & 15);
            int cb = ks * 8 + (lane >> 4) * 4;
            ldsm4(pa, sptr(&sQP[row * ASTR + cb]));
            #pragma unroll
            for (int df = 0; df < 8; df++) {
                unsigned bv[2];
                bv[0] = sV[(ks * 8 + tig) * ASTR + df * 8 + g];
                bv[1] = sV[(ks * 8 + tig + 4) * ASTR + df * 8 + g];
                mma8(O[df], pa, bv);
            }
        }
    }

    // epilogue
    float inv0 = 1.f / l0, inv1 = 1.f / l1;
    int r = qt * 64 + warp * 16 + g;
    #pragma unroll
    for (int df = 0; df < 8; df++) {
        int c = h * HD + df * 8 + tig * 2;
        *(float2*)(o + (size_t)(b * TSEQ + r) * HID + c) =
            make_float2(O[df][0] * inv0, O[df][1] * inv0);
        *(float2*)(o + (size_t)(b * TSEQ + r + 8) * HID + c) =
            make_float2(O[df][2] * inv1, O[df][3] * inv1);
    }
}

// ---------------------------------------------------------------------------
extern "C" void kernel_launch(void* const* d_in, const int* in_sizes, int n_in,
                              void* d_out, int out_size)
{
    const float* x   = (const float*)d_in[0];
    const float* Wq  = (const float*)d_in[1];
    const float* Wkv = (const float*)d_in[2];
    const float* Wo  = (const float*)d_in[3];
    float* out = (float*)d_out;

    float *gq, *gkv, *gatt;
    cudaGetSymbolAddress((void**)&gq, g_q);
    cudaGetSymbolAddress((void**)&gkv, g_kv);
    cudaGetSymbolAddress((void**)&gatt, g_att);

    cudaFuncSetAttribute(attn_tf32,
                         cudaFuncAttributeMaxDynamicSharedMemorySize, ATT_SMEM);

    // fused q & kv projections: 24 n-blocks (16 for Wq, 8 for Wkv)
    gemm_qkv<<<dim3(24, BT / 128), 256>>>(x, Wq, Wkv, gq, gkv);
    attn_tf32<<<dim3(TSEQ / 64, 16, 2), 128, ATT_SMEM>>>(gq, gkv, gatt);
    gemm_tf32<<<dim3(HID / 64, BT / 128), 256>>>(gatt, Wo, out, HID, HID);
}

// round 7
// speedup vs baseline: 4.8243x; 1.6026x over previous
#include <cuda_runtime.h>
#include <cuda_fp16.h>
#include <math.h>

#define BT   4096
#define HID  1024
#define TSEQ 2048
#define KVW  512
#define HD   64

__device__ float g_q[(size_t)BT * HID];
__device__ float g_kv[(size_t)BT * KVW];
__device__ float g_att[(size_t)BT * HID];

// ---------------------------------------------------------------------------
// fp16 helpers
// ---------------------------------------------------------------------------
__device__ __forceinline__ unsigned h2u(half2 h) { return *(unsigned*)&h; }
__device__ __forceinline__ unsigned f2h2(float a, float b) {
    half2 h = __float22half2_rn(make_float2(a, b));
    return h2u(h);
}
// mma.m16n8k16 f16 inputs, f32 accumulate
__device__ __forceinline__ void mma16(float* d, const unsigned* a, const unsigned* b) {
    asm volatile(
        "mma.sync.aligned.m16n8k16.row.col.f32.f16.f16.f32 "
        "{%0,%1,%2,%3},{%4,%5,%6,%7},{%8,%9},{%0,%1,%2,%3};\n"
        : "+f"(d[0]), "+f"(d[1]), "+f"(d[2]), "+f"(d[3])
        : "r"(a[0]), "r"(a[1]), "r"(a[2]), "r"(a[3]), "r"(b[0]), "r"(b[1]));
}
__device__ __forceinline__ void ldsm4(unsigned* r, unsigned addr) {
    asm volatile("ldmatrix.sync.aligned.m8n8.x4.shared.b16 {%0,%1,%2,%3}, [%4];"
                 : "=r"(r[0]), "=r"(r[1]), "=r"(r[2]), "=r"(r[3]) : "r"(addr));
}
__device__ __forceinline__ void ldsm2(unsigned* r, unsigned addr) {
    asm volatile("ldmatrix.sync.aligned.m8n8.x2.shared.b16 {%0,%1}, [%2];"
                 : "=r"(r[0]), "=r"(r[1]) : "r"(addr));
}
__device__ __forceinline__ void ldsm2t(unsigned* r, unsigned addr) {
    asm volatile("ldmatrix.sync.aligned.m8n8.x2.trans.shared.b16 {%0,%1}, [%2];"
                 : "=r"(r[0]), "=r"(r[1]) : "r"(addr));
}
__device__ __forceinline__ unsigned sptr(const void* p) {
    return (unsigned)__cvta_generic_to_shared(p);
}

// ---------------------------------------------------------------------------
// fp16 GEMM core: C[M,N] = A[M,K] @ B[K,N]. BM=128, BN=64, BK=32, 256 threads
// 8 warps (4m x 2n), warp tile 32x32 = 2 mfrag x 4 nfrag, 2 ksteps of k16.
// ---------------------------------------------------------------------------
#define GAS 40   // sA row stride (halves): 32 + 8 pad (80B rows)
#define GBS 72   // sB row stride (halves): 64 + 8 pad (144B rows)

__device__ __forceinline__ void gemm_core(
    const float* __restrict__ A, const float* __restrict__ B,
    float* __restrict__ C, int m0, int n0, int N, int K,
    half* sA, half* sB)
{
    const int t = threadIdx.x, lane = t & 31, warp = t >> 5;
    const int wm = warp & 3, wn = warp >> 2;
    const int g = lane >> 2, tig = lane & 3;

    float acc[2][4][4] = {};

    for (int k0 = 0; k0 < K; k0 += 32) {
        // A tile 128x32 -> half, uint2 (8B) stores
        #pragma unroll
        for (int u = 0; u < 4; u++) {
            int id = t + 256 * u;
            int row = id >> 3, kq = id & 7;
            float4 v = *(const float4*)(A + (size_t)(m0 + row) * K + k0 + kq * 4);
            *(uint2*)&sA[row * GAS + kq * 4] =
                make_uint2(f2h2(v.x, v.y), f2h2(v.z, v.w));
        }
        // B tile 32x64 -> half
        #pragma unroll
        for (int u = 0; u < 2; u++) {
            int id = t + 256 * u;
            int kr = id >> 4, nq = id & 15;
            float4 v = *(const float4*)(B + (size_t)(k0 + kr) * N + n0 + nq * 4);
            *(uint2*)&sB[kr * GBS + nq * 4] =
                make_uint2(f2h2(v.x, v.y), f2h2(v.z, v.w));
        }
        __syncthreads();

        #pragma unroll
        for (int ks = 0; ks < 2; ks++) {
            unsigned af[2][4];
            #pragma unroll
            for (int mf = 0; mf < 2; mf++) {
                int row = wm * 32 + mf * 16 + (lane & 15);
                int col = ks * 16 + (lane >> 4) * 8;
                ldsm4(af[mf], sptr(&sA[row * GAS + col]));
            }
            #pragma unroll
            for (int nf = 0; nf < 4; nf++) {
                // B[k][n] row-major -> trans load, rows = k
                unsigned bf[2];
                ldsm2t(bf, sptr(&sB[(ks * 16 + (lane & 15)) * GBS
                                    + wn * 32 + nf * 8]));
                #pragma unroll
                for (int mf = 0; mf < 2; mf++)
                    mma16(acc[mf][nf], af[mf], bf);
            }
        }
        __syncthreads();
    }

    #pragma unroll
    for (int mf = 0; mf < 2; mf++)
        #pragma unroll
        for (int nf = 0; nf < 4; nf++) {
            int r = m0 + wm * 32 + mf * 16 + g;
            int c = n0 + wn * 32 + nf * 8 + tig * 2;
            *(float2*)(C + (size_t)r * N + c) =
                make_float2(acc[mf][nf][0], acc[mf][nf][1]);
            *(float2*)(C + (size_t)(r + 8) * N + c) =
                make_float2(acc[mf][nf][2], acc[mf][nf][3]);
        }
}

__global__ __launch_bounds__(256) void gemm_h(
    const float* __restrict__ A, const float* __restrict__ B,
    float* __restrict__ C, int N, int K)
{
    __shared__ half sA[128 * GAS];
    __shared__ half sB[32 * GBS];
    gemm_core(A, B, C, blockIdx.y * 128, blockIdx.x * 64, N, K, sA, sB);
}

// Fused Q + KV projection: blockIdx.x 0..15 -> Wq, 16..23 -> Wkv
__global__ __launch_bounds__(256) void gemm_qkv(
    const float* __restrict__ x,
    const float* __restrict__ Wq, const float* __restrict__ Wkv,
    float* __restrict__ q, float* __restrict__ kvo)
{
    __shared__ half sA[128 * GAS];
    __shared__ half sB[32 * GBS];
    int bx = blockIdx.x;
    if (bx < 16)
        gemm_core(x, Wq, q, blockIdx.y * 128, bx * 64, HID, HID, sA, sB);
    else
        gemm_core(x, Wkv, kvo, blockIdx.y * 128, (bx - 16) * 64, KVW, HID, sA, sB);
}

// ---------------------------------------------------------------------------
// fp16 flash attention. Grid (T/64, H, B), 128 threads (4 warps).
// Warp w owns q-rows [w*16, w*16+16). Q frags in registers, sQP reused for P.
// ---------------------------------------------------------------------------
#define ASTR 72   // 64 + 8 pad (144B rows)

__global__ __launch_bounds__(128) void attn_h(
    const float* __restrict__ q, const float* __restrict__ kv,
    float* __restrict__ o)
{
    __shared__ half sQP[64 * ASTR];  // Q (prologue) then P [r][c]
    __shared__ half sK[64 * ASTR];   // [c][d]
    __shared__ half sV[64 * ASTR];   // [c][d]

    const int t = threadIdx.x, lane = t & 31, warp = t >> 5;
    const int g = lane >> 2, tig = lane & 3;
    const int qt = gridDim.x - 1 - blockIdx.x;  // long tiles first
    const int h = blockIdx.y, b = blockIdx.z;
    const int kvh = h >> 2;

    const size_t qbase  = (size_t)b * TSEQ * HID + (size_t)h * HD;
    const size_t kvbase = (size_t)b * TSEQ * KVW + (size_t)kvh * HD;

    // Q tile (pre-scaled by 1/8) -> sQP as half
    #pragma unroll
    for (int u = 0; u < 8; u++) {
        int id = t + 128 * u;
        int r = id >> 4, dq = id & 15;
        float4 v = *(const float4*)(q + qbase + (size_t)(qt * 64 + r) * HID + dq * 4);
        *(uint2*)&sQP[r * ASTR + dq * 4] =
            make_uint2(f2h2(v.x * 0.125f, v.y * 0.125f),
                       f2h2(v.z * 0.125f, v.w * 0.125f));
    }
    __syncthreads();

    // Q fragments to registers (4 ksteps of k16 over d=64)
    unsigned qa[4][4];
    {
        int row = warp * 16 + (lane & 15);
        int cb = (lane >> 4) * 8;
        #pragma unroll
        for (int ks = 0; ks < 4; ks++)
            ldsm4(qa[ks], sptr(&sQP[row * ASTR + ks * 16 + cb]));
    }

    float mr0 = -INFINITY, mr1 = -INFINITY, l0 = 0.f, l1 = 0.f;
    float O[8][4] = {};

    for (int kt = 0; kt <= qt; kt++) {
        __syncthreads();  // prior-tile sK/sV reads done; Q frags loaded

        // K and V tiles (64x64 halves each), [c][d] layout
        #pragma unroll
        for (int u = 0; u < 8; u++) {
            int id = t + 128 * u;
            int r = id >> 4, dq = id & 15;
            const float* rowp = kv + kvbase + (size_t)(kt * 64 + r) * KVW;
            float4 kk = *(const float4*)(rowp + dq * 4);
            *(uint2*)&sK[r * ASTR + dq * 4] =
                make_uint2(f2h2(kk.x, kk.y), f2h2(kk.z, kk.w));
            float4 vv = *(const float4*)(rowp + 256 + dq * 4);
            *(uint2*)&sV[r * ASTR + dq * 4] =
                make_uint2(f2h2(vv.x, vv.y), f2h2(vv.z, vv.w));
        }
        __syncthreads();

        // S = Q K^T (warp: 16 x 64). sK is [n=c][k=d] -> non-trans ldsm2.
        float s[8][4] = {};
        #pragma unroll
        for (int ks = 0; ks < 4; ks++) {
            #pragma unroll
            for (int nf = 0; nf < 8; nf++) {
                unsigned bf[2];
                ldsm2(bf, sptr(&sK[(nf * 8 + (lane & 7)) * ASTR
                                   + ks * 16 + ((lane >> 3) & 1) * 8]));
                mma16(s[nf], qa[ks], bf);
            }
        }

        // causal mask (diagonal tile only)
        if (kt == qt) {
            int r0 = qt * 64 + warp * 16 + g;
            #pragma unroll
            for (int nf = 0; nf < 8; nf++) {
                int col = kt * 64 + nf * 8 + tig * 2;
                if (col     > r0)     s[nf][0] = -INFINITY;
                if (col + 1 > r0)     s[nf][1] = -INFINITY;
                if (col     > r0 + 8) s[nf][2] = -INFINITY;
                if (col + 1 > r0 + 8) s[nf][3] = -INFINITY;
            }
        }

        // online softmax: thread owns rows g (regs 0,1) and g+8 (regs 2,3)
        float mx0 = -INFINITY, mx1 = -INFINITY;
        #pragma unroll
        for (int nf = 0; nf < 8; nf++) {
            mx0 = fmaxf(mx0, fmaxf(s[nf][0], s[nf][1]));
            mx1 = fmaxf(mx1, fmaxf(s[nf][2], s[nf][3]));
        }
        #pragma unroll
        for (int off = 1; off < 4; off <<= 1) {
            mx0 = fmaxf(mx0, __shfl_xor_sync(0xffffffffu, mx0, off));
            mx1 = fmaxf(mx1, __shfl_xor_sync(0xffffffffu, mx1, off));
        }
        float nm0 = fmaxf(mr0, mx0), nm1 = fmaxf(mr1, mx1);
        float a0 = __expf(mr0 - nm0), a1 = __expf(mr1 - nm1);
        float rs0 = 0.f, rs1 = 0.f;
        #pragma unroll
        for (int nf = 0; nf < 8; nf++) {
            s[nf][0] = __expf(s[nf][0] - nm0);
            s[nf][1] = __expf(s[nf][1] - nm0);
            s[nf][2] = __expf(s[nf][2] - nm1);
            s[nf][3] = __expf(s[nf][3] - nm1);
            rs0 += s[nf][0] + s[nf][1];
            rs1 += s[nf][2] + s[nf][3];
        }
        #pragma unroll
        for (int off = 1; off < 4; off <<= 1) {
            rs0 += __shfl_xor_sync(0xffffffffu, rs0, off);
            rs1 += __shfl_xor_sync(0xffffffffu, rs1, off);
        }
        l0 = l0 * a0 + rs0;  l1 = l1 * a1 + rs1;
        mr0 = nm0;           mr1 = nm1;
        #pragma unroll
        for (int df = 0; df < 8; df++) {
            O[df][0] *= a0; O[df][1] *= a0;
            O[df][2] *= a1; O[df][3] *= a1;
        }

        // P -> sQP (warp-private rows), half2 stores
        {
            int r = warp * 16 + g;
            #pragma unroll
            for (int nf = 0; nf < 8; nf++) {
                int c = nf * 8 + tig * 2;
                *(unsigned*)&sQP[r * ASTR + c]       = f2h2(s[nf][0], s[nf][1]);
                *(unsigned*)&sQP[(r + 8) * ASTR + c] = f2h2(s[nf][2], s[nf][3]);
            }
        }
        __syncwarp();

        // O += P @ V.  sV is [k=c][n=d] row-major -> trans ldsm2.
        #pragma unroll
        for (int ks = 0; ks < 4; ks++) {
            unsigned pa[4];
            int row = warp * 16 + (lane & 15);
            int cb = ks * 16 + (lane >> 4) * 8;
            ldsm4(pa, sptr(&sQP[row * ASTR + cb]));
            #pragma unroll
            for (int df = 0; df < 8; df++) {
                unsigned bf[2];
                ldsm2t(bf, sptr(&sV[(ks * 16 + (lane & 15)) * ASTR + df * 8]));
                mma16(O[df], pa, bf);
            }
        }
    }

    // epilogue
    float inv0 = 1.f / l0, inv1 = 1.f / l1;
    int r = qt * 64 + warp * 16 + g;
    #pragma unroll
    for (int df = 0; df < 8; df++) {
        int c = h * HD + df * 8 + tig * 2;
        *(float2*)(o + (size_t)(b * TSEQ + r) * HID + c) =
            make_float2(O[df][0] * inv0, O[df][1] * inv0);
        *(float2*)(o + (size_t)(b * TSEQ + r + 8) * HID + c) =
            make_float2(O[df][2] * inv1, O[df][3] * inv1);
    }
}

// ---------------------------------------------------------------------------
extern "C" void kernel_launch(void* const* d_in, const int* in_sizes, int n_in,
                              void* d_out, int out_size)
{
    const float* x   = (const float*)d_in[0];
    const float* Wq  = (const float*)d_in[1];
    const float* Wkv = (const float*)d_in[2];
    const float* Wo  = (const float*)d_in[3];
    float* out = (float*)d_out;

    float *gq, *gkv, *gatt;
    cudaGetSymbolAddress((void**)&gq, g_q);
    cudaGetSymbolAddress((void**)&gkv, g_kv);
    cudaGetSymbolAddress((void**)&gatt, g_att);

    gemm_qkv<<<dim3(24, BT / 128), 256>>>(x, Wq, Wkv, gq, gkv);
    attn_h<<<dim3(TSEQ / 64, 16, 2), 128>>>(gq, gkv, gatt);
    gemm_h<<<dim3(HID / 64, BT / 128), 256>>>(gatt, Wo, out, HID, HID);
}

// round 8
// speedup vs baseline: 7.0755x; 1.4666x over previous
#include <cuda_runtime.h>
#include <cuda_fp16.h>
#include <math.h>

#define BT   4096
#define HID  1024
#define TSEQ 2048
#define KVW  512
#define HD   64

// fp16 scratch (device globals — no allocation allowed)
__device__ __align__(256) half g_xh[(size_t)BT * HID];
__device__ __align__(256) half g_wqh[(size_t)HID * HID];
__device__ __align__(256) half g_wkvh[(size_t)HID * KVW];
__device__ __align__(256) half g_woh[(size_t)HID * HID];
__device__ __align__(256) half g_qh[(size_t)BT * HID];
__device__ __align__(256) half g_kvh[(size_t)BT * KVW];
__device__ __align__(256) half g_atth[(size_t)BT * HID];

// ---------------------------------------------------------------------------
// helpers
// ---------------------------------------------------------------------------
__device__ __forceinline__ unsigned f2h2(float a, float b) {
    half2 h = __float22half2_rn(make_float2(a, b));
    return *(unsigned*)&h;
}
__device__ __forceinline__ void mma16(float* d, const unsigned* a, const unsigned* b) {
    asm volatile(
        "mma.sync.aligned.m16n8k16.row.col.f32.f16.f16.f32 "
        "{%0,%1,%2,%3},{%4,%5,%6,%7},{%8,%9},{%0,%1,%2,%3};\n"
        : "+f"(d[0]), "+f"(d[1]), "+f"(d[2]), "+f"(d[3])
        : "r"(a[0]), "r"(a[1]), "r"(a[2]), "r"(a[3]), "r"(b[0]), "r"(b[1]));
}
__device__ __forceinline__ void ldsm4(unsigned* r, unsigned addr) {
    asm volatile("ldmatrix.sync.aligned.m8n8.x4.shared.b16 {%0,%1,%2,%3}, [%4];"
                 : "=r"(r[0]), "=r"(r[1]), "=r"(r[2]), "=r"(r[3]) : "r"(addr));
}
__device__ __forceinline__ void ldsm2(unsigned* r, unsigned addr) {
    asm volatile("ldmatrix.sync.aligned.m8n8.x2.shared.b16 {%0,%1}, [%2];"
                 : "=r"(r[0]), "=r"(r[1]) : "r"(addr));
}
__device__ __forceinline__ void ldsm2t(unsigned* r, unsigned addr) {
    asm volatile("ldmatrix.sync.aligned.m8n8.x2.trans.shared.b16 {%0,%1}, [%2];"
                 : "=r"(r[0]), "=r"(r[1]) : "r"(addr));
}
__device__ __forceinline__ unsigned sptr(const void* p) {
    return (unsigned)__cvta_generic_to_shared(p);
}
__device__ __forceinline__ void cpa16(unsigned dst, const void* src) {
    asm volatile("cp.async.cg.shared.global [%0], [%1], 16;" :: "r"(dst), "l"(src));
}
__device__ __forceinline__ void cp_commit() {
    asm volatile("cp.async.commit_group;");
}
template<int N> __device__ __forceinline__ void cp_wait() {
    asm volatile("cp.async.wait_group %0;" :: "n"(N));
}

// ---------------------------------------------------------------------------
// fp32 -> fp16 convert (vectorized)
// ---------------------------------------------------------------------------
__global__ __launch_bounds__(256) void conv_f2h(
    const float4* __restrict__ in, uint2* __restrict__ out, int n4)
{
    int i = blockIdx.x * 256 + threadIdx.x;
    if (i < n4) {
        float4 v = in[i];
        out[i] = make_uint2(f2h2(v.x, v.y), f2h2(v.z, v.w));
    }
}

// ---------------------------------------------------------------------------
// fp16 GEMM, cp.async 3-stage pipeline. C[M,N] = A[M,K] @ B[K,N].
// BM=128, BN=64, BK=32, 256 thr, 8 warps (4m x 2n), warp tile 32x32.
// ---------------------------------------------------------------------------
#define GAS 40   // sA row stride (halves): 32 + 8 pad (80B rows)
#define GBS 72   // sB row stride (halves): 64 + 8 pad (144B rows)

template<bool HALF_OUT>
__device__ __forceinline__ void gemm_core(
    const half* __restrict__ A, const half* __restrict__ B,
    void* __restrict__ Cv, int m0, int n0, int N, int K,
    half* sA, half* sB)   // sA: 3*128*GAS, sB: 3*32*GBS
{
    const int t = threadIdx.x, lane = t & 31, warp = t >> 5;
    const int wm = warp & 3, wn = warp >> 2;
    const int g = lane >> 2, tig = lane & 3;
    const int KT = K >> 5;

    const int a_row = t >> 2, a_ch = t & 3;       // 2 chunks/thread (u loop)
    const int b_row = t >> 3, b_ch = t & 7;       // 1 chunk/thread

    auto issue = [&](int kt, int s) {
        int k0 = kt * 32;
        half* dA = sA + s * 128 * GAS;
        half* dB = sB + s * 32 * GBS;
        #pragma unroll
        for (int u = 0; u < 2; u++) {
            int row = a_row + u * 64;
            cpa16(sptr(&dA[row * GAS + a_ch * 8]),
                  A + (size_t)(m0 + row) * K + k0 + a_ch * 8);
        }
        cpa16(sptr(&dB[b_row * GBS + b_ch * 8]),
              B + (size_t)(k0 + b_row) * N + n0 + b_ch * 8);
        cp_commit();
    };

    float acc[2][4][4] = {};

    issue(0, 0);
    issue(1, 1);
    cp_wait<1>();
    __syncthreads();

    for (int kt = 0; kt < KT; kt++) {
        int cur = kt % 3;
        if (kt + 2 < KT) issue(kt + 2, (kt + 2) % 3);

        half* cA = sA + cur * 128 * GAS;
        half* cB = sB + cur * 32 * GBS;

        #pragma unroll
        for (int ks = 0; ks < 2; ks++) {
            unsigned af[2][4];
            #pragma unroll
            for (int mf = 0; mf < 2; mf++) {
                int row = wm * 32 + mf * 16 + (lane & 15);
                int col = ks * 16 + (lane >> 4) * 8;
                ldsm4(af[mf], sptr(&cA[row * GAS + col]));
            }
            #pragma unroll
            for (int nf = 0; nf < 4; nf++) {
                unsigned bf[2];
                ldsm2t(bf, sptr(&cB[(ks * 16 + (lane & 15)) * GBS
                                    + wn * 32 + nf * 8]));
                #pragma unroll
                for (int mf = 0; mf < 2; mf++)
                    mma16(acc[mf][nf], af[mf], bf);
            }
        }

        if (kt + 1 < KT) {
            if (kt + 2 < KT) cp_wait<1>(); else cp_wait<0>();
            __syncthreads();
        }
    }

    #pragma unroll
    for (int mf = 0; mf < 2; mf++)
        #pragma unroll
        for (int nf = 0; nf < 4; nf++) {
            int r = m0 + wm * 32 + mf * 16 + g;
            int c = n0 + wn * 32 + nf * 8 + tig * 2;
            if (HALF_OUT) {
                half* C = (half*)Cv;
                *(unsigned*)&C[(size_t)r * N + c] =
                    f2h2(acc[mf][nf][0], acc[mf][nf][1]);
                *(unsigned*)&C[(size_t)(r + 8) * N + c] =
                    f2h2(acc[mf][nf][2], acc[mf][nf][3]);
            } else {
                float* C = (float*)Cv;
                *(float2*)(C + (size_t)r * N + c) =
                    make_float2(acc[mf][nf][0], acc[mf][nf][1]);
                *(float2*)(C + (size_t)(r + 8) * N + c) =
                    make_float2(acc[mf][nf][2], acc[mf][nf][3]);
            }
        }
}

// Fused Q + KV projection: blockIdx.x 0..15 -> Wq, 16..23 -> Wkv. half out.
__global__ __launch_bounds__(256) void gemm_qkv(
    const half* __restrict__ x,
    const half* __restrict__ Wq, const half* __restrict__ Wkv,
    half* __restrict__ q, half* __restrict__ kvo)
{
    __shared__ half sA[3 * 128 * GAS];
    __shared__ half sB[3 * 32 * GBS];
    int bx = blockIdx.x;
    if (bx < 16)
        gemm_core<true>(x, Wq, q, blockIdx.y * 128, bx * 64, HID, HID, sA, sB);
    else
        gemm_core<true>(x, Wkv, kvo, blockIdx.y * 128, (bx - 16) * 64, KVW, HID, sA, sB);
}

// Output projection: half in, float out
__global__ __launch_bounds__(256) void gemm_wo(
    const half* __restrict__ A, const half* __restrict__ B,
    float* __restrict__ C)
{
    __shared__ half sA[3 * 128 * GAS];
    __shared__ half sB[3 * 32 * GBS];
    gemm_core<false>(A, B, C, blockIdx.y * 128, blockIdx.x * 64, HID, HID, sA, sB);
}

// ---------------------------------------------------------------------------
// fp16 flash attention, cp.async double-buffered K/V.
// Grid (T/64, H, B), 128 threads (4 warps). Warp w owns q-rows [w*16, w*16+16).
// ---------------------------------------------------------------------------
#define ASTR 72   // 64 + 8 pad (144B rows)

__global__ __launch_bounds__(128) void attn_h(
    const half* __restrict__ q, const half* __restrict__ kv,
    half* __restrict__ o)
{
    __shared__ half sQP[64 * ASTR];     // Q (prologue) then P [r][c]
    __shared__ half sK[2][64 * ASTR];   // [c][d]
    __shared__ half sV[2][64 * ASTR];   // [c][d]

    const int t = threadIdx.x, lane = t & 31, warp = t >> 5;
    const int g = lane >> 2, tig = lane & 3;
    const int qt = gridDim.x - 1 - blockIdx.x;  // long tiles first
    const int h = blockIdx.y, b = blockIdx.z;
    const int kvh = h >> 2;

    const size_t qbase  = (size_t)b * TSEQ * HID + (size_t)h * HD;
    const half* kvp = kv + (size_t)b * TSEQ * KVW + (size_t)kvh * HD;

    const int kv_c = t >> 3, kv_ch = t & 7;   // 8 rows per u-step of 16 (id>>3)

    auto issueKV = [&](int kt, int s) {
        #pragma unroll
        for (int u = 0; u < 4; u++) {
            int c = kv_c + u * 16;
            const half* rowp = kvp + (size_t)(kt * 64 + c) * KVW;
            cpa16(sptr(&sK[s][c * ASTR + kv_ch * 8]), rowp + kv_ch * 8);
            cpa16(sptr(&sV[s][c * ASTR + kv_ch * 8]), rowp + 256 + kv_ch * 8);
        }
        cp_commit();
    };

    // start KV(0) load immediately
    issueKV(0, 0);

    // Q tile (pre-scaled by 1/8) -> sQP
    const half2 sc = __float2half2_rn(0.125f);
    #pragma unroll
    for (int u = 0; u < 4; u++) {
        int id = t + 128 * u;
        int r = id >> 3, dq = id & 7;
        uint4 v = *(const uint4*)(q + qbase + (size_t)(qt * 64 + r) * HID + dq * 8);
        half2* hv = (half2*)&v;
        #pragma unroll
        for (int i = 0; i < 4; i++) hv[i] = __hmul2(hv[i], sc);
        *(uint4*)&sQP[r * ASTR + dq * 8] = v;
    }
    cp_wait<0>();
    __syncthreads();

    // Q fragments to registers (sQP free after this)
    unsigned qa[4][4];
    {
        int row = warp * 16 + (lane & 15);
        int cb = (lane >> 4) * 8;
        #pragma unroll
        for (int ks = 0; ks < 4; ks++)
            ldsm4(qa[ks], sptr(&sQP[row * ASTR + ks * 16 + cb]));
    }

    float mr0 = -INFINITY, mr1 = -INFINITY, l0 = 0.f, l1 = 0.f;
    float O[8][4] = {};

    for (int kt = 0; kt <= qt; kt++) {
        int cur = kt & 1;
        if (kt < qt) issueKV(kt + 1, cur ^ 1);

        // S = Q K^T (warp: 16 x 64)
        float s[8][4] = {};
        #pragma unroll
        for (int ks = 0; ks < 4; ks++) {
            #pragma unroll
            for (int nf = 0; nf < 8; nf++) {
                unsigned bf[2];
                ldsm2(bf, sptr(&sK[cur][(nf * 8 + (lane & 7)) * ASTR
                                        + ks * 16 + ((lane >> 3) & 1) * 8]));
                mma16(s[nf], qa[ks], bf);
            }
        }

        // causal mask (diagonal tile only)
        if (kt == qt) {
            int r0 = qt * 64 + warp * 16 + g;
            #pragma unroll
            for (int nf = 0; nf < 8; nf++) {
                int col = kt * 64 + nf * 8 + tig * 2;
                if (col     > r0)     s[nf][0] = -INFINITY;
                if (col + 1 > r0)     s[nf][1] = -INFINITY;
                if (col     > r0 + 8) s[nf][2] = -INFINITY;
                if (col + 1 > r0 + 8) s[nf][3] = -INFINITY;
            }
        }

        // online softmax
        float mx0 = -INFINITY, mx1 = -INFINITY;
        #pragma unroll
        for (int nf = 0; nf < 8; nf++) {
            mx0 = fmaxf(mx0, fmaxf(s[nf][0], s[nf][1]));
            mx1 = fmaxf(mx1, fmaxf(s[nf][2], s[nf][3]));
        }
        #pragma unroll
        for (int off = 1; off < 4; off <<= 1) {
            mx0 = fmaxf(mx0, __shfl_xor_sync(0xffffffffu, mx0, off));
            mx1 = fmaxf(mx1, __shfl_xor_sync(0xffffffffu, mx1, off));
        }
        float nm0 = fmaxf(mr0, mx0), nm1 = fmaxf(mr1, mx1);
        float a0 = __expf(mr0 - nm0), a1 = __expf(mr1 - nm1);
        float rs0 = 0.f, rs1 = 0.f;
        #pragma unroll
        for (int nf = 0; nf < 8; nf++) {
            s[nf][0] = __expf(s[nf][0] - nm0);
            s[nf][1] = __expf(s[nf][1] - nm0);
            s[nf][2] = __expf(s[nf][2] - nm1);
            s[nf][3] = __expf(s[nf][3] - nm1);
            rs0 += s[nf][0] + s[nf][1];
            rs1 += s[nf][2] + s[nf][3];
        }
        #pragma unroll
        for (int off = 1; off < 4; off <<= 1) {
            rs0 += __shfl_xor_sync(0xffffffffu, rs0, off);
            rs1 += __shfl_xor_sync(0xffffffffu, rs1, off);
        }
        l0 = l0 * a0 + rs0;  l1 = l1 * a1 + rs1;
        mr0 = nm0;           mr1 = nm1;
        #pragma unroll
        for (int df = 0; df < 8; df++) {
            O[df][0] *= a0; O[df][1] *= a0;
            O[df][2] *= a1; O[df][3] *= a1;
        }

        // P -> sQP (warp-private rows)
        {
            int r = warp * 16 + g;
            #pragma unroll
            for (int nf = 0; nf < 8; nf++) {
                int c = nf * 8 + tig * 2;
                *(unsigned*)&sQP[r * ASTR + c]       = f2h2(s[nf][0], s[nf][1]);
                *(unsigned*)&sQP[(r + 8) * ASTR + c] = f2h2(s[nf][2], s[nf][3]);
            }
        }
        __syncwarp();

        // O += P @ V
        #pragma unroll
        for (int ks = 0; ks < 4; ks++) {
            unsigned pa[4];
            int row = warp * 16 + (lane & 15);
            int cb = ks * 16 + (lane >> 4) * 8;
            ldsm4(pa, sptr(&sQP[row * ASTR + cb]));
            #pragma unroll
            for (int df = 0; df < 8; df++) {
                unsigned bf[2];
                ldsm2t(bf, sptr(&sV[cur][(ks * 16 + (lane & 15)) * ASTR + df * 8]));
                mma16(O[df], pa, bf);
            }
        }

        if (kt < qt) {
            cp_wait<0>();
            __syncthreads();
        }
    }

    // epilogue: half output for Wo GEMM
    float inv0 = 1.f / l0, inv1 = 1.f / l1;
    int r = qt * 64 + warp * 16 + g;
    #pragma unroll
    for (int df = 0; df < 8; df++) {
        int c = h * HD + df * 8 + tig * 2;
        *(unsigned*)&o[(size_t)(b * TSEQ + r) * HID + c] =
            f2h2(O[df][0] * inv0, O[df][1] * inv0);
        *(unsigned*)&o[(size_t)(b * TSEQ + r + 8) * HID + c] =
            f2h2(O[df][2] * inv1, O[df][3] * inv1);
    }
}

// ---------------------------------------------------------------------------
extern "C" void kernel_launch(void* const* d_in, const int* in_sizes, int n_in,
                              void* d_out, int out_size)
{
    const float* x   = (const float*)d_in[0];
    const float* Wq  = (const float*)d_in[1];
    const float* Wkv = (const float*)d_in[2];
    const float* Wo  = (const float*)d_in[3];
    float* out = (float*)d_out;

    half *xh, *wqh, *wkvh, *woh, *qh, *kvh, *atth;
    cudaGetSymbolAddress((void**)&xh,   g_xh);
    cudaGetSymbolAddress((void**)&wqh,  g_wqh);
    cudaGetSymbolAddress((void**)&wkvh, g_wkvh);
    cudaGetSymbolAddress((void**)&woh,  g_woh);
    cudaGetSymbolAddress((void**)&qh,   g_qh);
    cudaGetSymbolAddress((void**)&kvh,  g_kvh);
    cudaGetSymbolAddress((void**)&atth, g_atth);

    // fp32 -> fp16 conversions
    int nx = BT * HID / 4, nq = HID * HID / 4, nk = HID * KVW / 4;
    conv_f2h<<<(nx + 255) / 256, 256>>>((const float4*)x,   (uint2*)xh,   nx);
    conv_f2h<<<(nq + 255) / 256, 256>>>((const float4*)Wq,  (uint2*)wqh,  nq);
    conv_f2h<<<(nk + 255) / 256, 256>>>((const float4*)Wkv, (uint2*)wkvh, nk);
    conv_f2h<<<(nq + 255) / 256, 256>>>((const float4*)Wo,  (uint2*)woh,  nq);

    gemm_qkv<<<dim3(24, BT / 128), 256>>>(xh, wqh, wkvh, qh, kvh);
    attn_h<<<dim3(TSEQ / 64, 16, 2), 128>>>(qh, kvh, atth);
    gemm_wo<<<dim3(HID / 64, BT / 128), 256>>>(atth, woh, out);
}